// round 1
// baseline (speedup 1.0000x reference)
#include <cuda_runtime.h>
#include <math.h>

// Problem dims (fixed by the reference)
#define B_   4
#define T_   2048
#define D_   1024
#define H_   16
#define HD_  64
#define M_TOT (B_*T_)   // 8192 rows for the projection GEMMs

// Scratch (device globals: allocation-free rule). 4 x 32MB.
__device__ __align__(128) float g_q [M_TOT * D_];
__device__ __align__(128) float g_k [M_TOT * D_];
__device__ __align__(128) float g_v [M_TOT * D_];
__device__ __align__(128) float g_ao[M_TOT * D_];

// ---------------------------------------------------------------------------
// GEMM: C[M,N] = A[M,K] * W[N,K]^T   (both row-major, K-contiguous: "NT")
// 128x128 block tile, BK=16, 256 threads, 8x8 per thread. fp32.
// ---------------------------------------------------------------------------
__device__ __forceinline__ void gemm_nt_128x128(const float* __restrict__ A,
                                                const float* __restrict__ W,
                                                float* __restrict__ C)
{
    constexpr int N = D_;
    constexpr int K = D_;

    __shared__ float As[16][128];
    __shared__ float Bs[16][128];

    const int tid = threadIdx.x;
    const int tx  = tid & 15;        // 0..15  -> 8 output cols
    const int ty  = tid >> 4;        // 0..15  -> 8 output rows
    const int m0  = blockIdx.y * 128;
    const int n0  = blockIdx.x * 128;

    float acc[8][8];
#pragma unroll
    for (int i = 0; i < 8; i++)
#pragma unroll
        for (int j = 0; j < 8; j++) acc[i][j] = 0.f;

    for (int k0 = 0; k0 < K; k0 += 16) {
        // Load 128x16 tiles of A and W, transposed into smem [k][m]/[k][n].
#pragma unroll
        for (int it = 0; it < 2; it++) {
            int v   = tid + it * 256;      // 0..511
            int row = v >> 2;              // 0..127
            int c4  = (v & 3) << 2;        // 0,4,8,12
            float4 a = *(const float4*)(A + (size_t)(m0 + row) * K + k0 + c4);
            As[c4 + 0][row] = a.x; As[c4 + 1][row] = a.y;
            As[c4 + 2][row] = a.z; As[c4 + 3][row] = a.w;
            float4 b = *(const float4*)(W + (size_t)(n0 + row) * K + k0 + c4);
            Bs[c4 + 0][row] = b.x; Bs[c4 + 1][row] = b.y;
            Bs[c4 + 2][row] = b.z; Bs[c4 + 3][row] = b.w;
        }
        __syncthreads();

#pragma unroll
        for (int kk = 0; kk < 16; kk++) {
            float ra[8], rb[8];
            *(float4*)&ra[0] = *(const float4*)&As[kk][ty * 8];
            *(float4*)&ra[4] = *(const float4*)&As[kk][ty * 8 + 4];
            *(float4*)&rb[0] = *(const float4*)&Bs[kk][tx * 8];
            *(float4*)&rb[4] = *(const float4*)&Bs[kk][tx * 8 + 4];
#pragma unroll
            for (int i = 0; i < 8; i++)
#pragma unroll
                for (int j = 0; j < 8; j++)
                    acc[i][j] = fmaf(ra[i], rb[j], acc[i][j]);
        }
        __syncthreads();
    }

#pragma unroll
    for (int i = 0; i < 8; i++) {
        int row = m0 + ty * 8 + i;
#pragma unroll
        for (int j = 0; j < 8; j += 4) {
            float4 o = make_float4(acc[i][j], acc[i][j + 1], acc[i][j + 2], acc[i][j + 3]);
            *(float4*)(C + (size_t)row * N + n0 + tx * 8 + j) = o;
        }
    }
}

__global__ void __launch_bounds__(256)
gemm_qkv_kernel(const float* __restrict__ x,
                const float* __restrict__ wq,
                const float* __restrict__ wk,
                const float* __restrict__ wv)
{
    const float* W = (blockIdx.z == 0) ? wq : (blockIdx.z == 1) ? wk : wv;
    float*       C = (blockIdx.z == 0) ? g_q : (blockIdx.z == 1) ? g_k : g_v;
    gemm_nt_128x128(x, W, C);
}

__global__ void __launch_bounds__(256)
gemm_out_kernel(const float* __restrict__ wo, float* __restrict__ out)
{
    gemm_nt_128x128(g_ao, wo, out);
}

// ---------------------------------------------------------------------------
// RoPE applied in-place to g_q and g_k. Layout: (B,T,H,Hd), Hd=64, half=32.
// cos/sin: [T,64] with cos[t,d]==cos[t,d+32].
// ---------------------------------------------------------------------------
__global__ void rope_kernel(const float* __restrict__ cosp,
                            const float* __restrict__ sinp)
{
    int idx = blockIdx.x * blockDim.x + threadIdx.x;
    if (idx >= B_ * T_ * H_ * 32) return;
    int d = idx & 31;
    int h = (idx >> 5) & (H_ - 1);
    int t = (idx >> 9) & (T_ - 1);
    int b = idx >> 20;
    size_t base = (((size_t)b * T_ + t) * H_ + h) * HD_;
    float c0 = cosp[t * HD_ + d];
    float s0 = sinp[t * HD_ + d];

    float q1 = g_q[base + d], q2 = g_q[base + d + 32];
    g_q[base + d]      = q1 * c0 - q2 * s0;
    g_q[base + d + 32] = q2 * c0 + q1 * s0;

    float k1 = g_k[base + d], k2 = g_k[base + d + 32];
    g_k[base + d]      = k1 * c0 - k2 * s0;
    g_k[base + d + 32] = k2 * c0 + k1 * s0;
}

// ---------------------------------------------------------------------------
// Causal flash attention. One block = one (b,h,query-tile of 64).
// Br=Bc=64, Hd=64, online softmax, fp32, 256 threads (16x16, 4x4 micro-tile).
// Smem: Qs/Ks/Ps transposed (stride 65), Vs natural (stride 68 for f4 align).
// ---------------------------------------------------------------------------
#define FA_STRIDE_T 65
#define FA_STRIDE_V 68
#define FA_SMEM_BYTES ((3 * 64 * FA_STRIDE_T + 64 * FA_STRIDE_V) * 4)

__global__ void __launch_bounds__(256)
flash_kernel()
{
    extern __shared__ float sm[];
    float* Qs = sm;                              // [d][r]
    float* Ks = sm + 64 * FA_STRIDE_T;           // [d][c]
    float* Ps = sm + 2 * 64 * FA_STRIDE_T;       // [c][r]
    float* Vs = sm + 3 * 64 * FA_STRIDE_T;       // [c][dd]

    const int tid = threadIdx.x;
    const int tx  = tid & 15;                    // 4 cols
    const int ty  = tid >> 4;                    // 4 rows
    const int qt  = blockIdx.x;                  // query tile (0..31)
    const int bh  = blockIdx.y;                  // b*H + h
    const int b   = bh >> 4;
    const int h   = bh & 15;

    // element offset of (b, t=0, h, d=0); t-stride is D_=H*Hd
    const size_t head_base = ((size_t)b * T_ * H_ + h) * HD_;

    // Load Q tile transposed
    {
        const float* qg = g_q + head_base + (size_t)(qt * 64) * D_;
        for (int v = tid; v < 64 * 16; v += 256) {
            int r  = v >> 4;
            int d4 = (v & 15) << 2;
            float4 a = *(const float4*)(qg + (size_t)r * D_ + d4);
            Qs[(d4 + 0) * FA_STRIDE_T + r] = a.x;
            Qs[(d4 + 1) * FA_STRIDE_T + r] = a.y;
            Qs[(d4 + 2) * FA_STRIDE_T + r] = a.z;
            Qs[(d4 + 3) * FA_STRIDE_T + r] = a.w;
        }
    }

    float m[4], l[4], o[4][4];
#pragma unroll
    for (int i = 0; i < 4; i++) {
        m[i] = -INFINITY; l[i] = 0.f;
#pragma unroll
        for (int j = 0; j < 4; j++) o[i][j] = 0.f;
    }

    const float scale = 0.125f;   // 1/sqrt(64)

    for (int kt = 0; kt <= qt; kt++) {
        // Load K tile (transposed) and V tile (natural)
        const float* kg = g_k + head_base + (size_t)(kt * 64) * D_;
        const float* vg = g_v + head_base + (size_t)(kt * 64) * D_;
        for (int v = tid; v < 64 * 16; v += 256) {
            int c  = v >> 4;
            int d4 = (v & 15) << 2;
            float4 a = *(const float4*)(kg + (size_t)c * D_ + d4);
            Ks[(d4 + 0) * FA_STRIDE_T + c] = a.x;
            Ks[(d4 + 1) * FA_STRIDE_T + c] = a.y;
            Ks[(d4 + 2) * FA_STRIDE_T + c] = a.z;
            Ks[(d4 + 3) * FA_STRIDE_T + c] = a.w;
            float4 vv = *(const float4*)(vg + (size_t)c * D_ + d4);
            *(float4*)&Vs[c * FA_STRIDE_V + d4] = vv;
        }
        __syncthreads();

        // S = Q K^T (4x4 per thread)
        float s[4][4];
#pragma unroll
        for (int i = 0; i < 4; i++)
#pragma unroll
            for (int j = 0; j < 4; j++) s[i][j] = 0.f;

        for (int d = 0; d < 64; d++) {
            float qr[4], kc[4];
#pragma unroll
            for (int i = 0; i < 4; i++) qr[i] = Qs[d * FA_STRIDE_T + ty * 4 + i];
#pragma unroll
            for (int j = 0; j < 4; j++) kc[j] = Ks[d * FA_STRIDE_T + tx * 4 + j];
#pragma unroll
            for (int i = 0; i < 4; i++)
#pragma unroll
                for (int j = 0; j < 4; j++)
                    s[i][j] = fmaf(qr[i], kc[j], s[i][j]);
        }

        // Scale + causal mask (only the diagonal tile needs masking)
        if (kt == qt) {
#pragma unroll
            for (int i = 0; i < 4; i++)
#pragma unroll
                for (int j = 0; j < 4; j++) {
                    int r = ty * 4 + i, c = tx * 4 + j;
                    s[i][j] = (c <= r) ? s[i][j] * scale : -1e30f;
                }
        } else {
#pragma unroll
            for (int i = 0; i < 4; i++)
#pragma unroll
                for (int j = 0; j < 4; j++) s[i][j] *= scale;
        }

        // Online softmax: row reductions across the 16 tx-lanes (same half-warp)
        float tmax[4];
#pragma unroll
        for (int i = 0; i < 4; i++) {
            tmax[i] = s[i][0];
#pragma unroll
            for (int j = 1; j < 4; j++) tmax[i] = fmaxf(tmax[i], s[i][j]);
        }
#pragma unroll
        for (int off = 8; off >= 1; off >>= 1)
#pragma unroll
            for (int i = 0; i < 4; i++)
                tmax[i] = fmaxf(tmax[i], __shfl_xor_sync(0xffffffffu, tmax[i], off));

        float rsum[4];
#pragma unroll
        for (int i = 0; i < 4; i++) {
            float mn    = fmaxf(m[i], tmax[i]);
            float alpha = __expf(m[i] - mn);
            m[i] = mn;
            l[i] *= alpha;
#pragma unroll
            for (int j = 0; j < 4; j++) o[i][j] *= alpha;
            float su = 0.f;
#pragma unroll
            for (int j = 0; j < 4; j++) {
                s[i][j] = __expf(s[i][j] - mn);
                su += s[i][j];
            }
            rsum[i] = su;
        }
#pragma unroll
        for (int off = 8; off >= 1; off >>= 1)
#pragma unroll
            for (int i = 0; i < 4; i++)
                rsum[i] += __shfl_xor_sync(0xffffffffu, rsum[i], off);
#pragma unroll
        for (int i = 0; i < 4; i++) l[i] += rsum[i];

        // Write P transposed [c][r]
#pragma unroll
        for (int i = 0; i < 4; i++)
#pragma unroll
            for (int j = 0; j < 4; j++)
                Ps[(tx * 4 + j) * FA_STRIDE_T + (ty * 4 + i)] = s[i][j];
        __syncthreads();

        // O += P V
        for (int c = 0; c < 64; c++) {
            float pr[4];
#pragma unroll
            for (int i = 0; i < 4; i++) pr[i] = Ps[c * FA_STRIDE_T + ty * 4 + i];
            float4 vv = *(const float4*)&Vs[c * FA_STRIDE_V + tx * 4];
            float rv[4] = {vv.x, vv.y, vv.z, vv.w};
#pragma unroll
            for (int i = 0; i < 4; i++)
#pragma unroll
                for (int j = 0; j < 4; j++)
                    o[i][j] = fmaf(pr[i], rv[j], o[i][j]);
        }
        __syncthreads();
    }

    // Finalize: divide by l and store to g_ao in (B,T,H,Hd) layout
    float* og = g_ao + head_base;
#pragma unroll
    for (int i = 0; i < 4; i++) {
        float inv = 1.0f / l[i];
        int t = qt * 64 + ty * 4 + i;
        float4 w = make_float4(o[i][0] * inv, o[i][1] * inv, o[i][2] * inv, o[i][3] * inv);
        *(float4*)(og + (size_t)t * D_ + tx * 4) = w;
    }
}

// ---------------------------------------------------------------------------
// Harness entry. Inputs: x, cos, sin, w_q, w_k, w_v, w_o (all fp32).
// ---------------------------------------------------------------------------
extern "C" void kernel_launch(void* const* d_in, const int* in_sizes, int n_in,
                              void* d_out, int out_size)
{
    const float* x    = (const float*)d_in[0];
    const float* cosp = (const float*)d_in[1];
    const float* sinp = (const float*)d_in[2];
    const float* wq   = (const float*)d_in[3];
    const float* wk   = (const float*)d_in[4];
    const float* wv   = (const float*)d_in[5];
    const float* wo   = (const float*)d_in[6];
    float* out        = (float*)d_out;

    // 1) QKV projections (fused over grid.z)
    {
        dim3 grid(D_ / 128, M_TOT / 128, 3);
        gemm_qkv_kernel<<<grid, 256>>>(x, wq, wk, wv);
    }

    // 2) RoPE in-place on q, k
    {
        int total = B_ * T_ * H_ * 32;
        rope_kernel<<<(total + 255) / 256, 256>>>(cosp, sinp);
    }

    // 3) Causal flash attention -> g_ao in (B,T,H*Hd) layout
    {
        cudaFuncSetAttribute(flash_kernel,
                             cudaFuncAttributeMaxDynamicSharedMemorySize,
                             FA_SMEM_BYTES);
        dim3 grid(T_ / 64, B_ * H_);
        flash_kernel<<<grid, 256, FA_SMEM_BYTES>>>();
    }

    // 4) Output projection
    {
        dim3 grid(D_ / 128, M_TOT / 128, 1);
        gemm_out_kernel<<<grid, 256>>>(wo, out);
    }
}

// round 3
// speedup vs baseline: 1.5653x; 1.5653x over previous
#include <cuda_runtime.h>
#include <cuda_bf16.h>
#include <math.h>
#include <stdint.h>

// Problem dims (fixed by the reference)
#define B_   4
#define T_   2048
#define D_   1024
#define H_   16
#define HD_  64
#define M_TOT (B_*T_)   // 8192
#define DD_  (D_*D_)

// ---------------------------------------------------------------------------
// Device-global scratch (allocation-free rule)
// ---------------------------------------------------------------------------
__device__ __align__(128) float g_q [M_TOT * D_];
__device__ __align__(128) float g_k [M_TOT * D_];
__device__ __align__(128) float g_v [M_TOT * D_];
__device__ __align__(128) float g_ao[M_TOT * D_];

__device__ __align__(128) __nv_bfloat16 g_xh [M_TOT * D_];
__device__ __align__(128) __nv_bfloat16 g_xl [M_TOT * D_];
__device__ __align__(128) __nv_bfloat16 g_aoh[M_TOT * D_];
__device__ __align__(128) __nv_bfloat16 g_aol[M_TOT * D_];
__device__ __align__(128) __nv_bfloat16 g_wh [4 * DD_];   // q,k,v,o
__device__ __align__(128) __nv_bfloat16 g_wl [4 * DD_];

// ---------------------------------------------------------------------------
// Helpers (all target-independent PTX: sm_80-era, safe for plain sm_103)
// ---------------------------------------------------------------------------
__device__ __forceinline__ uint32_t smem_u32(const void* p) {
    uint32_t a;
    asm("{ .reg .u64 t; cvta.to.shared.u64 t, %1; cvt.u32.u64 %0, t; }"
        : "=r"(a) : "l"(p));
    return a;
}

__device__ __forceinline__ void cp16(uint32_t dst, const void* src) {
    asm volatile("cp.async.cg.shared.global [%0], [%1], 16;"
                 :: "r"(dst), "l"(src));
}

__device__ __forceinline__ void ldsm4(uint32_t& r0, uint32_t& r1,
                                      uint32_t& r2, uint32_t& r3, uint32_t a) {
    asm volatile("ldmatrix.sync.aligned.m8n8.x4.shared.b16 {%0,%1,%2,%3}, [%4];"
                 : "=r"(r0), "=r"(r1), "=r"(r2), "=r"(r3) : "r"(a));
}

__device__ __forceinline__ void mma16816(float* c,
                                         uint32_t a0, uint32_t a1,
                                         uint32_t a2, uint32_t a3,
                                         uint32_t b0, uint32_t b1) {
    asm volatile("mma.sync.aligned.m16n8k16.row.col.f32.bf16.bf16.f32 "
                 "{%0,%1,%2,%3}, {%4,%5,%6,%7}, {%8,%9}, {%0,%1,%2,%3};"
                 : "+f"(c[0]), "+f"(c[1]), "+f"(c[2]), "+f"(c[3])
                 : "r"(a0), "r"(a1), "r"(a2), "r"(a3), "r"(b0), "r"(b1));
}

// ---------------------------------------------------------------------------
// fp32 -> (bf16 hi, bf16 lo) split conversions (globals referenced in-kernel,
// so no cudaGetSymbolAddress is needed on the host side)
// ---------------------------------------------------------------------------
__device__ __forceinline__ void split4(float4 a, uint2& hp, uint2& lp) {
    __nv_bfloat16 h0 = __float2bfloat16(a.x);
    __nv_bfloat16 h1 = __float2bfloat16(a.y);
    __nv_bfloat16 h2 = __float2bfloat16(a.z);
    __nv_bfloat16 h3 = __float2bfloat16(a.w);
    __nv_bfloat16 l0 = __float2bfloat16(a.x - __bfloat162float(h0));
    __nv_bfloat16 l1 = __float2bfloat16(a.y - __bfloat162float(h1));
    __nv_bfloat16 l2 = __float2bfloat16(a.z - __bfloat162float(h2));
    __nv_bfloat16 l3 = __float2bfloat16(a.w - __bfloat162float(h3));
    hp.x = (uint32_t)__bfloat16_as_ushort(h0) | ((uint32_t)__bfloat16_as_ushort(h1) << 16);
    hp.y = (uint32_t)__bfloat16_as_ushort(h2) | ((uint32_t)__bfloat16_as_ushort(h3) << 16);
    lp.x = (uint32_t)__bfloat16_as_ushort(l0) | ((uint32_t)__bfloat16_as_ushort(l1) << 16);
    lp.y = (uint32_t)__bfloat16_as_ushort(l2) | ((uint32_t)__bfloat16_as_ushort(l3) << 16);
}

__global__ void __launch_bounds__(256)
split_x_kernel(const float* __restrict__ src)
{
    int i = blockIdx.x * 256 + threadIdx.x;
    if (i >= M_TOT * D_ / 4) return;
    uint2 hp, lp;
    split4(((const float4*)src)[i], hp, lp);
    ((uint2*)g_xh)[i] = hp;
    ((uint2*)g_xl)[i] = lp;
}

__global__ void __launch_bounds__(256)
split_w_kernel(const float* __restrict__ src, int widx)
{
    int i = blockIdx.x * 256 + threadIdx.x;
    if (i >= DD_ / 4) return;
    uint2 hp, lp;
    split4(((const float4*)src)[i], hp, lp);
    ((uint2*)(g_wh + (size_t)widx * DD_))[i] = hp;
    ((uint2*)(g_wl + (size_t)widx * DD_))[i] = lp;
}

__global__ void __launch_bounds__(256)
split_ao_kernel()
{
    int i = blockIdx.x * 256 + threadIdx.x;
    if (i >= M_TOT * D_ / 4) return;
    uint2 hp, lp;
    split4(((const float4*)g_ao)[i], hp, lp);
    ((uint2*)g_aoh)[i] = hp;
    ((uint2*)g_aol)[i] = lp;
}

// ---------------------------------------------------------------------------
// mma.sync bf16x2-split GEMM: C[M,N] = A[M,K] * W[N,K]^T
// CTA tile 128x128, BK=32 bf16, 8 warps (4 along M x 2 along N),
// 2-stage cp.async pipeline, padded smem rows (80B) for conflict-free ldmatrix.
// ---------------------------------------------------------------------------
#define ROWB 40                       // smem row stride in bf16 (80 bytes)
#define STAGE_BYTES (4 * 128 * ROWB * 2)   // Ah,Al,Bh,Bl each 128 rows -> 40960
#define GEMM_SMEM_B (2 * STAGE_BYTES)      // 81920

__device__ void gemm_core(const __nv_bfloat16* __restrict__ Ah,
                          const __nv_bfloat16* __restrict__ Al,
                          const __nv_bfloat16* __restrict__ Bh,
                          const __nv_bfloat16* __restrict__ Bl,
                          float* __restrict__ C)
{
    extern __shared__ __align__(128) char smem[];
    const uint32_t sb = smem_u32(smem);
    const int tid  = threadIdx.x;
    const int lane = tid & 31;
    const int wid  = tid >> 5;
    const int warp_m = wid & 3;       // 4 warps -> 32 rows each
    const int warp_n = wid >> 2;      // 2 warps -> 64 cols each
    const int m0 = blockIdx.y * 128;
    const int n0 = blockIdx.x * 128;

    const __nv_bfloat16* base[4] = {
        Ah + (size_t)m0 * D_, Al + (size_t)m0 * D_,
        Bh + (size_t)n0 * D_, Bl + (size_t)n0 * D_
    };

    // ldmatrix lane address pieces
    const int a_row = lane & 15;
    const int a_col = (lane >> 4) << 3;                       // 0 or 8
    const int b_row = (lane & 7) + ((lane >> 4) << 3);        // n-offset
    const int b_col = ((lane >> 3) & 1) << 3;                 // 0 or 8

    float acc[2][8][4];
#pragma unroll
    for (int mt = 0; mt < 2; mt++)
#pragma unroll
        for (int nt = 0; nt < 8; nt++)
#pragma unroll
            for (int r = 0; r < 4; r++) acc[mt][nt][r] = 0.f;

    auto issue = [&](int st, int k0) {
        const uint32_t dstb = sb + st * STAGE_BYTES;
#pragma unroll
        for (int i = 0; i < 8; i++) {
            const int arr = i >> 1;                  // compile-time per unroll
            int w   = ((i & 1) << 8) | tid;          // 0..511
            int row = w >> 2;
            int c   = w & 3;
            uint32_t dst = dstb + (uint32_t)(arr * 128 * ROWB + row * ROWB + c * 8) * 2;
            cp16(dst, base[arr] + (size_t)row * D_ + k0 + c * 8);
        }
        asm volatile("cp.async.commit_group;" ::: "memory");
    };

    issue(0, 0);
    const int NIT = D_ / 32;
    for (int ic = 0; ic < NIT; ic++) {
        if (ic + 1 < NIT) {
            issue((ic + 1) & 1, (ic + 1) * 32);
            asm volatile("cp.async.wait_group 1;" ::: "memory");
        } else {
            asm volatile("cp.async.wait_group 0;" ::: "memory");
        }
        __syncthreads();

        const uint32_t sa = sb + (ic & 1) * STAGE_BYTES;
#pragma unroll
        for (int ks = 0; ks < 2; ks++) {
            uint32_t ah[2][4], al_[2][4], bh[4][4], bl[4][4];
#pragma unroll
            for (int mt = 0; mt < 2; mt++) {
                uint32_t ra = sa + (uint32_t)((warp_m * 32 + mt * 16 + a_row) * ROWB
                                              + ks * 16 + a_col) * 2;
                ldsm4(ah[mt][0],  ah[mt][1],  ah[mt][2],  ah[mt][3],  ra);
                ldsm4(al_[mt][0], al_[mt][1], al_[mt][2], al_[mt][3], ra + 128 * ROWB * 2);
            }
#pragma unroll
            for (int pt = 0; pt < 4; pt++) {
                uint32_t rb = sa + (uint32_t)(2 * 128 * ROWB
                                              + (warp_n * 64 + pt * 16 + b_row) * ROWB
                                              + ks * 16 + b_col) * 2;
                ldsm4(bh[pt][0], bh[pt][1], bh[pt][2], bh[pt][3], rb);
                ldsm4(bl[pt][0], bl[pt][1], bl[pt][2], bl[pt][3], rb + 128 * ROWB * 2);
            }
            // pass 1: Ah * Bh ; pass 2: Ah * Bl ; pass 3: Al * Bh
#pragma unroll
            for (int mt = 0; mt < 2; mt++)
#pragma unroll
                for (int nt = 0; nt < 8; nt++) {
                    uint32_t* bp  = bh[nt >> 1];
                    uint32_t  b0  = bp[(nt & 1) * 2], b1 = bp[(nt & 1) * 2 + 1];
                    uint32_t* blp = bl[nt >> 1];
                    uint32_t  c0  = blp[(nt & 1) * 2], c1 = blp[(nt & 1) * 2 + 1];
                    mma16816(acc[mt][nt], ah[mt][0], ah[mt][1], ah[mt][2], ah[mt][3], b0, b1);
                    mma16816(acc[mt][nt], ah[mt][0], ah[mt][1], ah[mt][2], ah[mt][3], c0, c1);
                    mma16816(acc[mt][nt], al_[mt][0], al_[mt][1], al_[mt][2], al_[mt][3], b0, b1);
                }
        }
        __syncthreads();
    }

    // Epilogue: direct fp32 stores from C fragments
    const int g = lane >> 2, t = lane & 3;
#pragma unroll
    for (int mt = 0; mt < 2; mt++) {
        int r0 = m0 + warp_m * 32 + mt * 16 + g;
#pragma unroll
        for (int nt = 0; nt < 8; nt++) {
            int col = n0 + warp_n * 64 + nt * 8 + t * 2;
            *(float2*)(C + (size_t)r0 * D_ + col) =
                make_float2(acc[mt][nt][0], acc[mt][nt][1]);
            *(float2*)(C + (size_t)(r0 + 8) * D_ + col) =
                make_float2(acc[mt][nt][2], acc[mt][nt][3]);
        }
    }
}

__global__ void __launch_bounds__(256)
gemm_qkv_mma()
{
    const int z = blockIdx.z;
    const __nv_bfloat16* Bh = g_wh + (size_t)z * DD_;
    const __nv_bfloat16* Bl = g_wl + (size_t)z * DD_;
    float* C = (z == 0) ? g_q : (z == 1) ? g_k : g_v;
    gemm_core(g_xh, g_xl, Bh, Bl, C);
}

__global__ void __launch_bounds__(256)
gemm_out_mma(float* __restrict__ out)
{
    gemm_core(g_aoh, g_aol, g_wh + (size_t)3 * DD_, g_wl + (size_t)3 * DD_, out);
}

// ---------------------------------------------------------------------------
// RoPE in-place on g_q and g_k. Layout (B,T,H,Hd), Hd=64.
// ---------------------------------------------------------------------------
__global__ void rope_kernel(const float* __restrict__ cosp,
                            const float* __restrict__ sinp)
{
    int idx = blockIdx.x * blockDim.x + threadIdx.x;
    if (idx >= B_ * T_ * H_ * 32) return;
    int d = idx & 31;
    int h = (idx >> 5) & (H_ - 1);
    int t = (idx >> 9) & (T_ - 1);
    int b = idx >> 20;
    size_t base = (((size_t)b * T_ + t) * H_ + h) * HD_;
    float c0 = cosp[t * HD_ + d];
    float s0 = sinp[t * HD_ + d];

    float q1 = g_q[base + d], q2 = g_q[base + d + 32];
    g_q[base + d]      = q1 * c0 - q2 * s0;
    g_q[base + d + 32] = q2 * c0 + q1 * s0;

    float k1 = g_k[base + d], k2 = g_k[base + d + 32];
    g_k[base + d]      = k1 * c0 - k2 * s0;
    g_k[base + d + 32] = k2 * c0 + k1 * s0;
}

// ---------------------------------------------------------------------------
// Causal flash attention, fp32. Br=128, Bc=64, 256 threads (16x16 grid,
// 8x4 micro-tile), float4 smem loads throughout.
// ---------------------------------------------------------------------------
#define SQ_ 132   // stride for [d][r 0..127] arrays (132*4 = 528, 16B multiple)
#define SK_ 68    // stride for [d][c 0..63] / [c][d 0..63]  (68*4 = 272)
#define FQ_OFF 0
#define FK_OFF (64 * SQ_)
#define FP_OFF (FK_OFF + 64 * SK_)
#define FV_OFF (FP_OFF + 64 * SQ_)
#define FA_SMEM_FLOATS (FV_OFF + 64 * SK_)
#define FA_SMEM_BYTES  (FA_SMEM_FLOATS * 4)   // 102400

__global__ void __launch_bounds__(256)
flash_kernel()
{
    extern __shared__ float sm[];
    float* Qs = sm + FQ_OFF;     // [d][r]   r: 128 queries
    float* Ks = sm + FK_OFF;     // [d][c]   c: 64 keys
    float* Ps = sm + FP_OFF;     // [c][r]
    float* Vs = sm + FV_OFF;     // [c][dd]

    const int tid = threadIdx.x;
    const int tx  = tid & 15;            // 4 cols each  -> 64
    const int ty  = tid >> 4;            // 8 rows each  -> 128
    const int qt  = blockIdx.x;          // query tile of 128 (0..15)
    const int bh  = blockIdx.y;
    const int b   = bh >> 4;
    const int h   = bh & 15;

    const size_t head_base = ((size_t)b * T_ * H_ + h) * HD_;

    // Load Q tile (128 x 64) transposed into Qs[d][r]
    {
        const float* qg = g_q + head_base + (size_t)(qt * 128) * D_;
#pragma unroll
        for (int v = tid; v < 128 * 16; v += 256) {
            int r  = v >> 4;
            int d4 = (v & 15) << 2;
            float4 a = *(const float4*)(qg + (size_t)r * D_ + d4);
            Qs[(d4 + 0) * SQ_ + r] = a.x;
            Qs[(d4 + 1) * SQ_ + r] = a.y;
            Qs[(d4 + 2) * SQ_ + r] = a.z;
            Qs[(d4 + 3) * SQ_ + r] = a.w;
        }
    }

    float m[8], l[8], o[8][4];
#pragma unroll
    for (int i = 0; i < 8; i++) {
        m[i] = -INFINITY; l[i] = 0.f;
#pragma unroll
        for (int j = 0; j < 4; j++) o[i][j] = 0.f;
    }

    const float scale = 0.125f;          // 1/sqrt(64)
    const int nkt = 2 * qt + 2;          // key tiles of 64

    for (int kt = 0; kt < nkt; kt++) {
        const float* kg = g_k + head_base + (size_t)(kt * 64) * D_;
        const float* vg = g_v + head_base + (size_t)(kt * 64) * D_;
#pragma unroll
        for (int v = tid; v < 64 * 16; v += 256) {
            int c  = v >> 4;
            int d4 = (v & 15) << 2;
            float4 a = *(const float4*)(kg + (size_t)c * D_ + d4);
            Ks[(d4 + 0) * SK_ + c] = a.x;
            Ks[(d4 + 1) * SK_ + c] = a.y;
            Ks[(d4 + 2) * SK_ + c] = a.z;
            Ks[(d4 + 3) * SK_ + c] = a.w;
            float4 vv = *(const float4*)(vg + (size_t)c * D_ + d4);
            *(float4*)&Vs[c * SK_ + d4] = vv;
        }
        __syncthreads();

        // S = Q K^T : 8x4 per thread, float4 smem reads
        float s[8][4];
#pragma unroll
        for (int i = 0; i < 8; i++)
#pragma unroll
            for (int j = 0; j < 4; j++) s[i][j] = 0.f;

#pragma unroll 4
        for (int d = 0; d < 64; d++) {
            float4 q0 = *(const float4*)&Qs[d * SQ_ + ty * 8];
            float4 q1 = *(const float4*)&Qs[d * SQ_ + ty * 8 + 4];
            float4 kc = *(const float4*)&Ks[d * SK_ + tx * 4];
            float qr[8] = {q0.x, q0.y, q0.z, q0.w, q1.x, q1.y, q1.z, q1.w};
            float kv[4] = {kc.x, kc.y, kc.z, kc.w};
#pragma unroll
            for (int i = 0; i < 8; i++)
#pragma unroll
                for (int j = 0; j < 4; j++)
                    s[i][j] = fmaf(qr[i], kv[j], s[i][j]);
        }

        // Scale + causal mask (only last two key tiles overlap the diagonal)
        if (kt >= 2 * qt) {
#pragma unroll
            for (int i = 0; i < 8; i++) {
                int r = qt * 128 + ty * 8 + i;
#pragma unroll
                for (int j = 0; j < 4; j++) {
                    int c = kt * 64 + tx * 4 + j;
                    s[i][j] = (c <= r) ? s[i][j] * scale : -1e30f;
                }
            }
        } else {
#pragma unroll
            for (int i = 0; i < 8; i++)
#pragma unroll
                for (int j = 0; j < 4; j++) s[i][j] *= scale;
        }

        // Online softmax; row reduction across the 16 tx lanes (half-warp)
        float tmax[8];
#pragma unroll
        for (int i = 0; i < 8; i++) {
            tmax[i] = fmaxf(fmaxf(s[i][0], s[i][1]), fmaxf(s[i][2], s[i][3]));
        }
#pragma unroll
        for (int off = 8; off >= 1; off >>= 1)
#pragma unroll
            for (int i = 0; i < 8; i++)
                tmax[i] = fmaxf(tmax[i], __shfl_xor_sync(0xffffffffu, tmax[i], off));

        float rsum[8];
#pragma unroll
        for (int i = 0; i < 8; i++) {
            float mn    = fmaxf(m[i], tmax[i]);
            float alpha = __expf(m[i] - mn);
            m[i] = mn;
            l[i] *= alpha;
#pragma unroll
            for (int j = 0; j < 4; j++) o[i][j] *= alpha;
            float su = 0.f;
#pragma unroll
            for (int j = 0; j < 4; j++) {
                s[i][j] = __expf(s[i][j] - mn);
                su += s[i][j];
            }
            rsum[i] = su;
        }
#pragma unroll
        for (int off = 8; off >= 1; off >>= 1)
#pragma unroll
            for (int i = 0; i < 8; i++)
                rsum[i] += __shfl_xor_sync(0xffffffffu, rsum[i], off);
#pragma unroll
        for (int i = 0; i < 8; i++) l[i] += rsum[i];

        // Write P transposed [c][r]
#pragma unroll
        for (int i = 0; i < 8; i++)
#pragma unroll
            for (int j = 0; j < 4; j++)
                Ps[(tx * 4 + j) * SQ_ + (ty * 8 + i)] = s[i][j];
        __syncthreads();

        // O += P V
#pragma unroll 4
        for (int c = 0; c < 64; c++) {
            float4 p0 = *(const float4*)&Ps[c * SQ_ + ty * 8];
            float4 p1 = *(const float4*)&Ps[c * SQ_ + ty * 8 + 4];
            float4 vv = *(const float4*)&Vs[c * SK_ + tx * 4];
            float pr[8] = {p0.x, p0.y, p0.z, p0.w, p1.x, p1.y, p1.z, p1.w};
            float rv[4] = {vv.x, vv.y, vv.z, vv.w};
#pragma unroll
            for (int i = 0; i < 8; i++)
#pragma unroll
                for (int j = 0; j < 4; j++)
                    o[i][j] = fmaf(pr[i], rv[j], o[i][j]);
        }
        __syncthreads();
    }

    // Finalize
    float* og = g_ao + head_base;
#pragma unroll
    for (int i = 0; i < 8; i++) {
        float inv = 1.0f / l[i];
        int t = qt * 128 + ty * 8 + i;
        float4 w = make_float4(o[i][0] * inv, o[i][1] * inv,
                               o[i][2] * inv, o[i][3] * inv);
        *(float4*)(og + (size_t)t * D_ + tx * 4) = w;
    }
}

// ---------------------------------------------------------------------------
// Harness entry
// ---------------------------------------------------------------------------
extern "C" void kernel_launch(void* const* d_in, const int* in_sizes, int n_in,
                              void* d_out, int out_size)
{
    const float* x    = (const float*)d_in[0];
    const float* cosp = (const float*)d_in[1];
    const float* sinp = (const float*)d_in[2];
    const float* wq   = (const float*)d_in[3];
    const float* wk   = (const float*)d_in[4];
    const float* wv   = (const float*)d_in[5];
    const float* wo   = (const float*)d_in[6];
    float* out        = (float*)d_out;

    cudaFuncSetAttribute(gemm_qkv_mma,
                         cudaFuncAttributeMaxDynamicSharedMemorySize, GEMM_SMEM_B);
    cudaFuncSetAttribute(gemm_out_mma,
                         cudaFuncAttributeMaxDynamicSharedMemorySize, GEMM_SMEM_B);
    cudaFuncSetAttribute(flash_kernel,
                         cudaFuncAttributeMaxDynamicSharedMemorySize, FA_SMEM_BYTES);

    // 0) fp32 -> bf16 hi/lo splits
    {
        int n4x = (M_TOT * D_) / 4;
        split_x_kernel<<<(n4x + 255) / 256, 256>>>(x);
        int n4w = DD_ / 4;
        split_w_kernel<<<(n4w + 255) / 256, 256>>>(wq, 0);
        split_w_kernel<<<(n4w + 255) / 256, 256>>>(wk, 1);
        split_w_kernel<<<(n4w + 255) / 256, 256>>>(wv, 2);
        split_w_kernel<<<(n4w + 255) / 256, 256>>>(wo, 3);
    }

    // 1) QKV projections (mma.sync bf16 split)
    {
        dim3 grid(D_ / 128, M_TOT / 128, 3);
        gemm_qkv_mma<<<grid, 256, GEMM_SMEM_B>>>();
    }

    // 2) RoPE in-place on q, k
    {
        int total = B_ * T_ * H_ * 32;
        rope_kernel<<<(total + 255) / 256, 256>>>(cosp, sinp);
    }

    // 3) Causal flash attention -> g_ao
    {
        dim3 grid(T_ / 128, B_ * H_);
        flash_kernel<<<grid, 256, FA_SMEM_BYTES>>>();
    }

    // 4) Split attention output, then output projection
    {
        int n4 = (M_TOT * D_) / 4;
        split_ao_kernel<<<(n4 + 255) / 256, 256>>>();
        dim3 grid(D_ / 128, M_TOT / 128, 1);
        gemm_out_mma<<<grid, 256, GEMM_SMEM_B>>>(out);
    }
}

// round 4
// speedup vs baseline: 2.5298x; 1.6162x over previous
#include <cuda_runtime.h>
#include <cuda_bf16.h>
#include <math.h>
#include <stdint.h>

// Problem dims (fixed by the reference)
#define B_   4
#define T_   2048
#define D_   1024
#define H_   16
#define HD_  64
#define M_TOT (B_*T_)   // 8192
#define DD_  (D_*D_)

// ---------------------------------------------------------------------------
// Device-global scratch (allocation-free rule). All bf16 hi/lo pairs.
// ---------------------------------------------------------------------------
__device__ __align__(128) __nv_bfloat16 g_xh [M_TOT * D_];
__device__ __align__(128) __nv_bfloat16 g_xl [M_TOT * D_];
__device__ __align__(128) __nv_bfloat16 g_qh [M_TOT * D_];
__device__ __align__(128) __nv_bfloat16 g_ql [M_TOT * D_];
__device__ __align__(128) __nv_bfloat16 g_kh [M_TOT * D_];
__device__ __align__(128) __nv_bfloat16 g_kl [M_TOT * D_];
__device__ __align__(128) __nv_bfloat16 g_vh [M_TOT * D_];
__device__ __align__(128) __nv_bfloat16 g_vl [M_TOT * D_];
__device__ __align__(128) __nv_bfloat16 g_aoh[M_TOT * D_];
__device__ __align__(128) __nv_bfloat16 g_aol[M_TOT * D_];
__device__ __align__(128) __nv_bfloat16 g_wh [4 * DD_];   // q,k,v,o
__device__ __align__(128) __nv_bfloat16 g_wl [4 * DD_];

// ---------------------------------------------------------------------------
// PTX helpers (target-independent, sm_80-era)
// ---------------------------------------------------------------------------
__device__ __forceinline__ uint32_t smem_u32(const void* p) {
    uint32_t a;
    asm("{ .reg .u64 t; cvta.to.shared.u64 t, %1; cvt.u32.u64 %0, t; }"
        : "=r"(a) : "l"(p));
    return a;
}

__device__ __forceinline__ void cp16(uint32_t dst, const void* src) {
    asm volatile("cp.async.cg.shared.global [%0], [%1], 16;"
                 :: "r"(dst), "l"(src));
}
#define CP_COMMIT() asm volatile("cp.async.commit_group;" ::: "memory")
#define CP_WAIT(n)  asm volatile("cp.async.wait_group %0;" :: "n"(n) : "memory")

__device__ __forceinline__ void ldsm4(uint32_t& r0, uint32_t& r1,
                                      uint32_t& r2, uint32_t& r3, uint32_t a) {
    asm volatile("ldmatrix.sync.aligned.m8n8.x4.shared.b16 {%0,%1,%2,%3}, [%4];"
                 : "=r"(r0), "=r"(r1), "=r"(r2), "=r"(r3) : "r"(a));
}
__device__ __forceinline__ void ldsm4t(uint32_t& r0, uint32_t& r1,
                                       uint32_t& r2, uint32_t& r3, uint32_t a) {
    asm volatile("ldmatrix.sync.aligned.m8n8.x4.trans.shared.b16 {%0,%1,%2,%3}, [%4];"
                 : "=r"(r0), "=r"(r1), "=r"(r2), "=r"(r3) : "r"(a));
}

__device__ __forceinline__ void mma16816(float* c,
                                         uint32_t a0, uint32_t a1,
                                         uint32_t a2, uint32_t a3,
                                         uint32_t b0, uint32_t b1) {
    asm volatile("mma.sync.aligned.m16n8k16.row.col.f32.bf16.bf16.f32 "
                 "{%0,%1,%2,%3}, {%4,%5,%6,%7}, {%8,%9}, {%0,%1,%2,%3};"
                 : "+f"(c[0]), "+f"(c[1]), "+f"(c[2]), "+f"(c[3])
                 : "r"(a0), "r"(a1), "r"(a2), "r"(a3), "r"(b0), "r"(b1));
}

// split fp32 pair -> packed bf16 hi pair + lo pair
__device__ __forceinline__ void split_pack2(float x, float y,
                                            uint32_t& hp, uint32_t& lp) {
    __nv_bfloat16 hx = __float2bfloat16(x);
    __nv_bfloat16 hy = __float2bfloat16(y);
    __nv_bfloat16 lx = __float2bfloat16(x - __bfloat162float(hx));
    __nv_bfloat16 ly = __float2bfloat16(y - __bfloat162float(hy));
    hp = (uint32_t)__bfloat16_as_ushort(hx) | ((uint32_t)__bfloat16_as_ushort(hy) << 16);
    lp = (uint32_t)__bfloat16_as_ushort(lx) | ((uint32_t)__bfloat16_as_ushort(ly) << 16);
}

// ---------------------------------------------------------------------------
// Input split kernels
// ---------------------------------------------------------------------------
__global__ void __launch_bounds__(256)
split_x_kernel(const float* __restrict__ src)
{
    int i = blockIdx.x * 256 + threadIdx.x;
    if (i >= M_TOT * D_ / 2) return;
    float2 a = ((const float2*)src)[i];
    uint32_t hp, lp;
    split_pack2(a.x, a.y, hp, lp);
    ((uint32_t*)g_xh)[i] = hp;
    ((uint32_t*)g_xl)[i] = lp;
}

__global__ void __launch_bounds__(256)
split_w_kernel(const float* __restrict__ src, int widx)
{
    int i = blockIdx.x * 256 + threadIdx.x;
    if (i >= DD_ / 2) return;
    float2 a = ((const float2*)src)[i];
    uint32_t hp, lp;
    split_pack2(a.x, a.y, hp, lp);
    ((uint32_t*)(g_wh + (size_t)widx * DD_))[i] = hp;
    ((uint32_t*)(g_wl + (size_t)widx * DD_))[i] = lp;
}

// ---------------------------------------------------------------------------
// mma.sync bf16x2-split GEMM: C[M,N] = A[M,K] * W[N,K]^T
// CTA tile 128x128, BK=32 bf16, 8 warps (4m x 2n), 2-stage cp.async pipeline.
// MODE 0: fp32 output.  MODE 1: RoPE + scale + bf16 split.  MODE 2: split only.
// ---------------------------------------------------------------------------
#define ROWB 40                            // smem row stride in bf16 (80 B)
#define STAGE_BYTES (4 * 128 * ROWB * 2)   // 40960
#define GEMM_SMEM_B (2 * STAGE_BYTES)      // 81920

template <int MODE>
__device__ void gemm_core(const __nv_bfloat16* __restrict__ Ah,
                          const __nv_bfloat16* __restrict__ Al,
                          const __nv_bfloat16* __restrict__ Bh,
                          const __nv_bfloat16* __restrict__ Bl,
                          float* __restrict__ Cf,
                          __nv_bfloat16* __restrict__ Ch,
                          __nv_bfloat16* __restrict__ Cl,
                          const float* __restrict__ cosp,
                          const float* __restrict__ sinp,
                          float qscale)
{
    extern __shared__ __align__(128) char smem[];
    const uint32_t sb = smem_u32(smem);
    const int tid  = threadIdx.x;
    const int lane = tid & 31;
    const int wid  = tid >> 5;
    const int warp_m = wid & 3;
    const int warp_n = wid >> 2;
    const int m0 = blockIdx.y * 128;
    const int n0 = blockIdx.x * 128;

    const __nv_bfloat16* base[4] = {
        Ah + (size_t)m0 * D_, Al + (size_t)m0 * D_,
        Bh + (size_t)n0 * D_, Bl + (size_t)n0 * D_
    };

    const int a_row = lane & 15;
    const int a_col = (lane >> 4) << 3;
    const int b_row = (lane & 7) + ((lane >> 4) << 3);
    const int b_col = ((lane >> 3) & 1) << 3;

    float acc[2][8][4];
#pragma unroll
    for (int mt = 0; mt < 2; mt++)
#pragma unroll
        for (int nt = 0; nt < 8; nt++)
#pragma unroll
            for (int r = 0; r < 4; r++) acc[mt][nt][r] = 0.f;

    auto issue = [&](int st, int k0) {
        const uint32_t dstb = sb + st * STAGE_BYTES;
#pragma unroll
        for (int i = 0; i < 8; i++) {
            const int arr = i >> 1;
            int w   = ((i & 1) << 8) | tid;
            int row = w >> 2;
            int c   = w & 3;
            uint32_t dst = dstb + (uint32_t)(arr * 128 * ROWB + row * ROWB + c * 8) * 2;
            cp16(dst, base[arr] + (size_t)row * D_ + k0 + c * 8);
        }
        CP_COMMIT();
    };

    issue(0, 0);
    const int NIT = D_ / 32;
    for (int ic = 0; ic < NIT; ic++) {
        if (ic + 1 < NIT) {
            issue((ic + 1) & 1, (ic + 1) * 32);
            CP_WAIT(1);
        } else {
            CP_WAIT(0);
        }
        __syncthreads();

        const uint32_t sa = sb + (ic & 1) * STAGE_BYTES;
#pragma unroll
        for (int ks = 0; ks < 2; ks++) {
            uint32_t ah[2][4], al_[2][4], bh[4][4], bl[4][4];
#pragma unroll
            for (int mt = 0; mt < 2; mt++) {
                uint32_t ra = sa + (uint32_t)((warp_m * 32 + mt * 16 + a_row) * ROWB
                                              + ks * 16 + a_col) * 2;
                ldsm4(ah[mt][0],  ah[mt][1],  ah[mt][2],  ah[mt][3],  ra);
                ldsm4(al_[mt][0], al_[mt][1], al_[mt][2], al_[mt][3], ra + 128 * ROWB * 2);
            }
#pragma unroll
            for (int pt = 0; pt < 4; pt++) {
                uint32_t rb = sa + (uint32_t)(2 * 128 * ROWB
                                              + (warp_n * 64 + pt * 16 + b_row) * ROWB
                                              + ks * 16 + b_col) * 2;
                ldsm4(bh[pt][0], bh[pt][1], bh[pt][2], bh[pt][3], rb);
                ldsm4(bl[pt][0], bl[pt][1], bl[pt][2], bl[pt][3], rb + 128 * ROWB * 2);
            }
#pragma unroll
            for (int mt = 0; mt < 2; mt++)
#pragma unroll
                for (int nt = 0; nt < 8; nt++) {
                    uint32_t* bp  = bh[nt >> 1];
                    uint32_t  b0  = bp[(nt & 1) * 2], b1 = bp[(nt & 1) * 2 + 1];
                    uint32_t* blp = bl[nt >> 1];
                    uint32_t  c0  = blp[(nt & 1) * 2], c1 = blp[(nt & 1) * 2 + 1];
                    mma16816(acc[mt][nt], ah[mt][0], ah[mt][1], ah[mt][2], ah[mt][3], b0, b1);
                    mma16816(acc[mt][nt], ah[mt][0], ah[mt][1], ah[mt][2], ah[mt][3], c0, c1);
                    mma16816(acc[mt][nt], al_[mt][0], al_[mt][1], al_[mt][2], al_[mt][3], b0, b1);
                }
        }
        __syncthreads();
    }

    const int g = lane >> 2, t2 = lane & 3;
    if (MODE == 0) {
#pragma unroll
        for (int mt = 0; mt < 2; mt++) {
            int r0 = m0 + warp_m * 32 + mt * 16 + g;
#pragma unroll
            for (int nt = 0; nt < 8; nt++) {
                int col = n0 + warp_n * 64 + nt * 8 + t2 * 2;
                *(float2*)(Cf + (size_t)r0 * D_ + col) =
                    make_float2(acc[mt][nt][0], acc[mt][nt][1]);
                *(float2*)(Cf + (size_t)(r0 + 8) * D_ + col) =
                    make_float2(acc[mt][nt][2], acc[mt][nt][3]);
            }
        }
    } else if (MODE == 1) {
        // RoPE (pairs d, d+32 are nt and nt+4 on the same thread) + scale + split
#pragma unroll
        for (int mt = 0; mt < 2; mt++) {
#pragma unroll
            for (int ri = 0; ri < 2; ri++) {
                int row = m0 + warp_m * 32 + mt * 16 + g + ri * 8;   // global token
                int t = row & (T_ - 1);
#pragma unroll
                for (int nt = 0; nt < 4; nt++) {
                    int d = nt * 8 + t2 * 2;                          // < 32
                    float2 cc = *(const float2*)(cosp + t * HD_ + d);
                    float2 ss = *(const float2*)(sinp + t * HD_ + d);
                    float v0 = acc[mt][nt][ri * 2],     v1 = acc[mt][nt][ri * 2 + 1];
                    float w0 = acc[mt][nt + 4][ri * 2], w1 = acc[mt][nt + 4][ri * 2 + 1];
                    float q0 = (v0 * cc.x - w0 * ss.x) * qscale;
                    float q1 = (v1 * cc.y - w1 * ss.y) * qscale;
                    float p0 = (w0 * cc.x + v0 * ss.x) * qscale;
                    float p1 = (w1 * cc.y + v1 * ss.y) * qscale;
                    int col = n0 + warp_n * 64 + nt * 8 + t2 * 2;
                    uint32_t hp, lp;
                    split_pack2(q0, q1, hp, lp);
                    *(uint32_t*)(Ch + (size_t)row * D_ + col) = hp;
                    *(uint32_t*)(Cl + (size_t)row * D_ + col) = lp;
                    split_pack2(p0, p1, hp, lp);
                    *(uint32_t*)(Ch + (size_t)row * D_ + col + 32) = hp;
                    *(uint32_t*)(Cl + (size_t)row * D_ + col + 32) = lp;
                }
            }
        }
    } else {
#pragma unroll
        for (int mt = 0; mt < 2; mt++) {
#pragma unroll
            for (int ri = 0; ri < 2; ri++) {
                int row = m0 + warp_m * 32 + mt * 16 + g + ri * 8;
#pragma unroll
                for (int nt = 0; nt < 8; nt++) {
                    int col = n0 + warp_n * 64 + nt * 8 + t2 * 2;
                    uint32_t hp, lp;
                    split_pack2(acc[mt][nt][ri * 2], acc[mt][nt][ri * 2 + 1], hp, lp);
                    *(uint32_t*)(Ch + (size_t)row * D_ + col) = hp;
                    *(uint32_t*)(Cl + (size_t)row * D_ + col) = lp;
                }
            }
        }
    }
}

__global__ void __launch_bounds__(256)
gemm_qkv_mma(const float* __restrict__ cosp, const float* __restrict__ sinp)
{
    const int z = blockIdx.z;
    if (z == 0)
        gemm_core<1>(g_xh, g_xl, g_wh, g_wl, nullptr, g_qh, g_ql, cosp, sinp, 0.125f);
    else if (z == 1)
        gemm_core<1>(g_xh, g_xl, g_wh + DD_, g_wl + DD_, nullptr, g_kh, g_kl, cosp, sinp, 1.0f);
    else
        gemm_core<2>(g_xh, g_xl, g_wh + 2 * (size_t)DD_, g_wl + 2 * (size_t)DD_,
                     nullptr, g_vh, g_vl, nullptr, nullptr, 1.0f);
}

__global__ void __launch_bounds__(256)
gemm_out_mma(float* __restrict__ out)
{
    gemm_core<0>(g_aoh, g_aol, g_wh + 3 * (size_t)DD_, g_wl + 3 * (size_t)DD_,
                 out, nullptr, nullptr, nullptr, nullptr, 1.0f);
}

// ---------------------------------------------------------------------------
// Flash attention on mma.sync (bf16 hi/lo 3-pass split).
// CTA: 8 warps, Br=128 (16 rows/warp), Bc=64, Hd=64.
// Q fragments register-resident; K/V double-buffered cp.async (stride 72 bf16).
// ---------------------------------------------------------------------------
#define FS    72                    // smem row stride in bf16 (144 B)
#define QH_E  0
#define QL_E  (128 * FS)            // 9216
#define KV_E  (2 * 128 * FS)        // 18432
#define ARR_E (64 * FS)             // 4608
#define STG_E (4 * ARR_E)           // 18432
#define FA_BYTES ((KV_E + 2 * STG_E) * 2)   // 110592

__global__ void __launch_bounds__(256)
flash_mma()
{
    extern __shared__ __align__(128) char fsmc[];
    const uint32_t sb = smem_u32(fsmc);
    const int tid = threadIdx.x, lane = tid & 31, wid = tid >> 5;
    const int qt = blockIdx.x, bh = blockIdx.y;
    const int b = bh >> 4, h = bh & 15;
    const int g = lane >> 2, t2 = lane & 3;
    const size_t qtok = (size_t)b * T_ + (size_t)qt * 128;

    // --- issue Q loads (hi+lo) ---
#pragma unroll
    for (int i = 0; i < 8; i++) {
        int v = tid + i * 256;                 // 0..2047
        int arr = v >> 10, rem = v & 1023;
        int row = rem >> 3, c = rem & 7;
        const __nv_bfloat16* src = arr ? g_ql : g_qh;
        cp16(sb + (uint32_t)((arr ? QL_E : QH_E) + row * FS + c * 8) * 2,
             src + (qtok + row) * D_ + h * 64 + c * 8);
    }

    auto issueKV = [&](int kt, int st) {
        const size_t tok = (size_t)b * T_ + (size_t)kt * 64;
        const __nv_bfloat16* srcs[4] = { g_kh, g_kl, g_vh, g_vl };
#pragma unroll
        for (int i = 0; i < 8; i++) {
            int v = tid + i * 256;             // 0..2047
            int arr = v >> 9, rem = v & 511;
            int row = rem >> 3, c = rem & 7;
            cp16(sb + (uint32_t)(KV_E + st * STG_E + arr * ARR_E + row * FS + c * 8) * 2,
                 srcs[arr] + (tok + row) * D_ + h * 64 + c * 8);
        }
        CP_COMMIT();
    };

    issueKV(0, 0);
    CP_WAIT(0);
    __syncthreads();

    // --- Q fragments into registers (rows fixed for this warp) ---
    uint32_t qh[4][4], ql[4][4];
    {
        uint32_t base_r = (uint32_t)((wid * 16 + (lane & 15)) * FS + ((lane >> 4) & 1) * 8);
#pragma unroll
        for (int kg = 0; kg < 4; kg++) {
            ldsm4(qh[kg][0], qh[kg][1], qh[kg][2], qh[kg][3],
                  sb + (QH_E + base_r + kg * 16) * 2);
            ldsm4(ql[kg][0], ql[kg][1], ql[kg][2], ql[kg][3],
                  sb + (QL_E + base_r + kg * 16) * 2);
        }
    }

    float o[8][4];
#pragma unroll
    for (int nt = 0; nt < 8; nt++)
#pragma unroll
        for (int j = 0; j < 4; j++) o[nt][j] = 0.f;
    float m0r = -INFINITY, m1r = -INFINITY, l0 = 0.f, l1 = 0.f;

    const int nkt = 2 * qt + 2;
    const int row0 = qt * 128 + wid * 16 + g;   // within-sequence row (r1 = row0+8)

    for (int kt = 0; kt < nkt; kt++) {
        if (kt + 1 < nkt) issueKV(kt + 1, (kt + 1) & 1);

        const uint32_t kb_h = sb + (uint32_t)(KV_E + (kt & 1) * STG_E) * 2;
        const uint32_t kb_l = kb_h + ARR_E * 2;
        const uint32_t vb_h = kb_h + 2 * ARR_E * 2;
        const uint32_t vb_l = kb_h + 3 * ARR_E * 2;

        // ---- S = Q K^T (3-pass split) ----
        float s[8][4];
#pragma unroll
        for (int nt = 0; nt < 8; nt++)
#pragma unroll
            for (int j = 0; j < 4; j++) s[nt][j] = 0.f;

#pragma unroll
        for (int kg = 0; kg < 4; kg++) {
            const uint32_t brow = (uint32_t)(((lane & 7) + ((lane >> 4) & 1) * 8) * FS
                                             + kg * 16 + ((lane >> 3) & 1) * 8) * 2;
#pragma unroll
            for (int pt = 0; pt < 4; pt++) {
                uint32_t kh0, kh1, kh2, kh3, kl0, kl1, kl2, kl3;
                uint32_t off = brow + (uint32_t)(pt * 16 * FS) * 2;
                ldsm4(kh0, kh1, kh2, kh3, kb_h + off);
                ldsm4(kl0, kl1, kl2, kl3, kb_l + off);
                mma16816(s[2 * pt],     qh[kg][0], qh[kg][1], qh[kg][2], qh[kg][3], kh0, kh1);
                mma16816(s[2 * pt],     qh[kg][0], qh[kg][1], qh[kg][2], qh[kg][3], kl0, kl1);
                mma16816(s[2 * pt],     ql[kg][0], ql[kg][1], ql[kg][2], ql[kg][3], kh0, kh1);
                mma16816(s[2 * pt + 1], qh[kg][0], qh[kg][1], qh[kg][2], qh[kg][3], kh2, kh3);
                mma16816(s[2 * pt + 1], qh[kg][0], qh[kg][1], qh[kg][2], qh[kg][3], kl2, kl3);
                mma16816(s[2 * pt + 1], ql[kg][0], ql[kg][1], ql[kg][2], ql[kg][3], kh2, kh3);
            }
        }

        // ---- causal mask (scale already folded into q) ----
        if (kt * 64 + 63 > qt * 128 + wid * 16) {
#pragma unroll
            for (int nt = 0; nt < 8; nt++) {
#pragma unroll
                for (int j = 0; j < 4; j++) {
                    int col = kt * 64 + nt * 8 + t2 * 2 + (j & 1);
                    int row = row0 + (j >> 1) * 8;
                    if (col > row) s[nt][j] = -1e30f;
                }
            }
        }

        // ---- online softmax ----
        float mx0 = -INFINITY, mx1 = -INFINITY;
#pragma unroll
        for (int nt = 0; nt < 8; nt++) {
            mx0 = fmaxf(mx0, fmaxf(s[nt][0], s[nt][1]));
            mx1 = fmaxf(mx1, fmaxf(s[nt][2], s[nt][3]));
        }
        mx0 = fmaxf(mx0, __shfl_xor_sync(0xffffffffu, mx0, 1));
        mx0 = fmaxf(mx0, __shfl_xor_sync(0xffffffffu, mx0, 2));
        mx1 = fmaxf(mx1, __shfl_xor_sync(0xffffffffu, mx1, 1));
        mx1 = fmaxf(mx1, __shfl_xor_sync(0xffffffffu, mx1, 2));

        float mn0 = fmaxf(m0r, mx0), mn1 = fmaxf(m1r, mx1);
        float al0 = __expf(m0r - mn0), al1 = __expf(m1r - mn1);
        m0r = mn0; m1r = mn1;

        float su0 = 0.f, su1 = 0.f;
#pragma unroll
        for (int nt = 0; nt < 8; nt++) {
            s[nt][0] = __expf(s[nt][0] - mn0);
            s[nt][1] = __expf(s[nt][1] - mn0);
            s[nt][2] = __expf(s[nt][2] - mn1);
            s[nt][3] = __expf(s[nt][3] - mn1);
            su0 += s[nt][0] + s[nt][1];
            su1 += s[nt][2] + s[nt][3];
        }
        su0 += __shfl_xor_sync(0xffffffffu, su0, 1);
        su0 += __shfl_xor_sync(0xffffffffu, su0, 2);
        su1 += __shfl_xor_sync(0xffffffffu, su1, 1);
        su1 += __shfl_xor_sync(0xffffffffu, su1, 2);
        l0 = l0 * al0 + su0;
        l1 = l1 * al1 + su1;

#pragma unroll
        for (int nt = 0; nt < 8; nt++) {
            o[nt][0] *= al0; o[nt][1] *= al0;
            o[nt][2] *= al1; o[nt][3] *= al1;
        }

        // ---- O += P V (3-pass split); P repacked from S fragments ----
#pragma unroll
        for (int kk = 0; kk < 4; kk++) {
            uint32_t pah[4], pal[4];
            split_pack2(s[2 * kk][0],     s[2 * kk][1],     pah[0], pal[0]);
            split_pack2(s[2 * kk][2],     s[2 * kk][3],     pah[1], pal[1]);
            split_pack2(s[2 * kk + 1][0], s[2 * kk + 1][1], pah[2], pal[2]);
            split_pack2(s[2 * kk + 1][2], s[2 * kk + 1][3], pah[3], pal[3]);

            const uint32_t vrow = (uint32_t)((kk * 16 + (lane & 7) + ((lane >> 3) & 1) * 8) * FS
                                             + ((lane >> 4) & 1) * 8) * 2;
#pragma unroll
            for (int dg = 0; dg < 4; dg++) {
                uint32_t vh0, vh1, vh2, vh3, vl0, vl1, vl2, vl3;
                uint32_t off = vrow + (uint32_t)(dg * 16) * 2;
                ldsm4t(vh0, vh1, vh2, vh3, vb_h + off);
                ldsm4t(vl0, vl1, vl2, vl3, vb_l + off);
                mma16816(o[2 * dg],     pah[0], pah[1], pah[2], pah[3], vh0, vh1);
                mma16816(o[2 * dg],     pah[0], pah[1], pah[2], pah[3], vl0, vl1);
                mma16816(o[2 * dg],     pal[0], pal[1], pal[2], pal[3], vh0, vh1);
                mma16816(o[2 * dg + 1], pah[0], pah[1], pah[2], pah[3], vh2, vh3);
                mma16816(o[2 * dg + 1], pah[0], pah[1], pah[2], pah[3], vl2, vl3);
                mma16816(o[2 * dg + 1], pal[0], pal[1], pal[2], pal[3], vh2, vh3);
            }
        }

        if (kt + 1 < nkt) CP_WAIT(0);
        __syncthreads();
    }

    // ---- epilogue: normalize, split, store bf16 hi/lo ----
    const float inv0 = 1.0f / l0, inv1 = 1.0f / l1;
    const size_t tok0 = qtok + (size_t)(wid * 16 + g);
#pragma unroll
    for (int nt = 0; nt < 8; nt++) {
        int col = h * 64 + nt * 8 + t2 * 2;
        uint32_t hp, lp;
        split_pack2(o[nt][0] * inv0, o[nt][1] * inv0, hp, lp);
        *(uint32_t*)(g_aoh + tok0 * D_ + col) = hp;
        *(uint32_t*)(g_aol + tok0 * D_ + col) = lp;
        split_pack2(o[nt][2] * inv1, o[nt][3] * inv1, hp, lp);
        *(uint32_t*)(g_aoh + (tok0 + 8) * D_ + col) = hp;
        *(uint32_t*)(g_aol + (tok0 + 8) * D_ + col) = lp;
    }
}

// ---------------------------------------------------------------------------
// Harness entry
// ---------------------------------------------------------------------------
extern "C" void kernel_launch(void* const* d_in, const int* in_sizes, int n_in,
                              void* d_out, int out_size)
{
    const float* x    = (const float*)d_in[0];
    const float* cosp = (const float*)d_in[1];
    const float* sinp = (const float*)d_in[2];
    const float* wq   = (const float*)d_in[3];
    const float* wk   = (const float*)d_in[4];
    const float* wv   = (const float*)d_in[5];
    const float* wo   = (const float*)d_in[6];
    float* out        = (float*)d_out;

    cudaFuncSetAttribute(gemm_qkv_mma,
                         cudaFuncAttributeMaxDynamicSharedMemorySize, GEMM_SMEM_B);
    cudaFuncSetAttribute(gemm_out_mma,
                         cudaFuncAttributeMaxDynamicSharedMemorySize, GEMM_SMEM_B);
    cudaFuncSetAttribute(flash_mma,
                         cudaFuncAttributeMaxDynamicSharedMemorySize, FA_BYTES);

    // 0) fp32 -> bf16 hi/lo splits (x, weights)
    {
        int n2x = (M_TOT * D_) / 2;
        split_x_kernel<<<(n2x + 255) / 256, 256>>>(x);
        int n2w = DD_ / 2;
        split_w_kernel<<<(n2w + 255) / 256, 256>>>(wq, 0);
        split_w_kernel<<<(n2w + 255) / 256, 256>>>(wk, 1);
        split_w_kernel<<<(n2w + 255) / 256, 256>>>(wv, 2);
        split_w_kernel<<<(n2w + 255) / 256, 256>>>(wo, 3);
    }

    // 1) QKV projections with fused RoPE + scale + bf16 split epilogue
    {
        dim3 grid(D_ / 128, M_TOT / 128, 3);
        gemm_qkv_mma<<<grid, 256, GEMM_SMEM_B>>>(cosp, sinp);
    }

    // 2) Causal flash attention on mma.sync -> g_aoh/g_aol
    {
        dim3 grid(T_ / 128, B_ * H_);
        flash_mma<<<grid, 256, FA_BYTES>>>();
    }

    // 3) Output projection
    {
        dim3 grid(D_ / 128, M_TOT / 128, 1);
        gemm_out_mma<<<grid, 256, GEMM_SMEM_B>>>(out);
    }
}